// round 8
// baseline (speedup 1.0000x reference)
#include <cuda_runtime.h>
#include <cuda_bf16.h>
#include <math.h>
#include <stdint.h>

#define Bn 8
#define Tn 1024
#define Cn 512
#define Hn 64
#define NREL 50
#define QK_SCALE 0.125f   // 64^-0.5
#define NQT 16
#define NCH 4
#define NWORK 40

// split-bf16 q,k (row-major [B*T][64]) and v transposed ([B][64][T])
__device__ __nv_bfloat16 g_qh[Bn * Tn * Hn];
__device__ __nv_bfloat16 g_ql[Bn * Tn * Hn];
__device__ __nv_bfloat16 g_kh[Bn * Tn * Hn];
__device__ __nv_bfloat16 g_kl[Bn * Tn * Hn];
__device__ __nv_bfloat16 g_vth[Bn * Hn * Tn];
__device__ __nv_bfloat16 g_vtl[Bn * Hn * Tn];

// split-bf16 W^T
__device__ __nv_bfloat16 g_wth[192 * Cn];
__device__ __nv_bfloat16 g_wtl[192 * Cn];

// split-KV partials + completion counters
__device__ float g_pacc[Bn * NQT * NCH][64 * 64];
__device__ float g_pm[Bn * NQT * NCH][64];
__device__ float g_pl[Bn * NQT * NCH][64];
__device__ int   g_cnt[Bn * NQT];

__constant__ unsigned char c_qt[NWORK] = {
    0,1,2,3, 4,4, 5,5, 6,6, 7,7,
    8,8,8, 9,9,9, 10,10,10, 11,11,11,
    12,12,12,12, 13,13,13,13, 14,14,14,14, 15,15,15,15};
__constant__ unsigned char c_ch[NWORK] = {
    0,0,0,0, 0,1, 0,1, 0,1, 0,1,
    0,1,2, 0,1,2, 0,1,2, 0,1,2,
    0,1,2,3, 0,1,2,3, 0,1,2,3, 0,1,2,3};

// ---------------------------------------------------------------------------
// helpers
// ---------------------------------------------------------------------------
__device__ __forceinline__ uint32_t smem_u32(const void* p) {
    uint32_t a;
    asm("{ .reg .u64 t; cvta.to.shared.u64 t, %1; cvt.u32.u64 %0, t; }"
        : "=r"(a) : "l"(p));
    return a;
}
#define LDM_X4(r0, r1, r2, r3, a) \
    asm volatile("ldmatrix.sync.aligned.m8n8.x4.shared.b16 {%0,%1,%2,%3}, [%4];" \
                 : "=r"(r0), "=r"(r1), "=r"(r2), "=r"(r3) : "r"(a))
#define LDM_X2(r0, r1, a) \
    asm volatile("ldmatrix.sync.aligned.m8n8.x2.shared.b16 {%0,%1}, [%2];" \
                 : "=r"(r0), "=r"(r1) : "r"(a))
#define MMA_BF16(d, a, b) \
    asm volatile("mma.sync.aligned.m16n8k16.row.col.f32.bf16.bf16.f32 " \
                 "{%0,%1,%2,%3}, {%4,%5,%6,%7}, {%8,%9}, {%0,%1,%2,%3};" \
                 : "+f"((d)[0]), "+f"((d)[1]), "+f"((d)[2]), "+f"((d)[3]) \
                 : "r"((a)[0]), "r"((a)[1]), "r"((a)[2]), "r"((a)[3]), \
                   "r"((b)[0]), "r"((b)[1]))

__device__ __forceinline__ void split2(float f0, float f1,
                                       uint32_t& h, uint32_t& l) {
    __nv_bfloat16 h0 = __float2bfloat16(f0), h1 = __float2bfloat16(f1);
    __nv_bfloat16 l0 = __float2bfloat16(f0 - __bfloat162float(h0));
    __nv_bfloat16 l1 = __float2bfloat16(f1 - __bfloat162float(h1));
    __nv_bfloat162 hh(h0, h1), ll(l0, l1);
    h = *(uint32_t*)&hh; l = *(uint32_t*)&ll;
}

// ---------------------------------------------------------------------------
// Weight convert + transpose (tiled, coalesced both sides). grid 24 x 256.
// Block = (mat, ktile): stages a 64k x 64n tile, emits g_wt[n][k] rows.
// Also resets combine counters.
// ---------------------------------------------------------------------------
__global__ __launch_bounds__(256) void cvt_w_kernel(
    const float* __restrict__ Wq, const float* __restrict__ Wk,
    const float* __restrict__ Wv)
{
    __shared__ __nv_bfloat16 th[64][72];   // [n][k]
    __shared__ __nv_bfloat16 tl[64][72];
    if (blockIdx.x == 0 && threadIdx.x < Bn * NQT) g_cnt[threadIdx.x] = 0;

    const int mat = blockIdx.x >> 3, kt = blockIdx.x & 7;
    const float* W = (mat == 0) ? Wq : (mat == 1 ? Wk : Wv);
    const int tid = threadIdx.x;

#pragma unroll
    for (int it = 0; it < 4; it++) {
        int f = it * 256 + tid;
        int k = f >> 4, nn = (f & 15) << 2;
        float4 v = *(const float4*)(W + (size_t)(kt * 64 + k) * Hn + nn);
        float vv[4] = {v.x, v.y, v.z, v.w};
#pragma unroll
        for (int j = 0; j < 4; j++) {
            __nv_bfloat16 h = __float2bfloat16(vv[j]);
            th[nn + j][k] = h;
            tl[nn + j][k] = __float2bfloat16(vv[j] - __bfloat162float(h));
        }
    }
    __syncthreads();
#pragma unroll
    for (int it = 0; it < 2; it++) {
        int f = it * 256 + tid;
        int n = f >> 3, kk = (f & 7) << 3;
        size_t dst = (size_t)(mat * 64 + n) * Cn + kt * 64 + kk;
        *(uint4*)(g_wth + dst) = *(uint4*)&th[n][kk];
        *(uint4*)(g_wtl + dst) = *(uint4*)&tl[n][kk];
    }
}

// ---------------------------------------------------------------------------
// QKV projection on mma.sync bf16 (split hi/lo). grid 128, 256 threads.
// ---------------------------------------------------------------------------
#define PAD 72
#define SM_AH 0
#define SM_AL 9216
#define SM_BH 18432
#define SM_BL 46080
#define QKV_SMEM 73728

__global__ __launch_bounds__(256, 1) void qkv_mma_kernel(const float* __restrict__ x)
{
    extern __shared__ char smem[];
    const uint32_t sb = smem_u32(smem);
    const int tid = threadIdx.x;
    const int wid = tid >> 5, lane = tid & 31;
    const int wm = wid >> 2, wn = wid & 3;
    const int m0 = blockIdx.x * 64;

    float acc[2][6][4];
#pragma unroll
    for (int mt = 0; mt < 2; mt++)
#pragma unroll
        for (int nt = 0; nt < 6; nt++)
#pragma unroll
            for (int e = 0; e < 4; e++) acc[mt][nt][e] = 0.f;

    const int aq = lane >> 3, ai = lane & 7;
    const int arow_off = (aq & 1) * 8 + ai;
    const int akoff = (aq >> 1) * 8;
    const int bi = lane & 7, bh8 = ((lane >> 3) & 1) * 8;

    for (int c = 0; c < 8; c++) {
        if (c) __syncthreads();
        const int kc = c * 64;
#pragma unroll
        for (int it = 0; it < 4; it++) {
            int f = it * 256 + tid;
            int r = f >> 4, kq = (f & 15) << 2;
            float4 v = *(const float4*)(x + (size_t)(m0 + r) * Cn + kc + kq);
            uint32_t h0, l0, h1, l1;
            split2(v.x, v.y, h0, l0);
            split2(v.z, v.w, h1, l1);
            uint32_t off = (uint32_t)(r * PAD + kq) * 2;
            *(uint2*)(smem + SM_AH + off) = make_uint2(h0, h1);
            *(uint2*)(smem + SM_AL + off) = make_uint2(l0, l1);
        }
#pragma unroll
        for (int it = 0; it < 6; it++) {
            int f = it * 256 + tid;
            int n = f >> 3, kq = (f & 7) << 3;
            uint32_t off = (uint32_t)(n * PAD + kq) * 2;
            *(uint4*)(smem + SM_BH + off) =
                *(const uint4*)(g_wth + (size_t)n * Cn + kc + kq);
            *(uint4*)(smem + SM_BL + off) =
                *(const uint4*)(g_wtl + (size_t)n * Cn + kc + kq);
        }
        __syncthreads();

#pragma unroll
        for (int ks = 0; ks < 4; ks++) {
            const int K = ks * 16;
            uint32_t ah[2][4], al[2][4];
#pragma unroll
            for (int mt = 0; mt < 2; mt++) {
                uint32_t ao = (uint32_t)((wm * 32 + mt * 16 + arow_off) * PAD
                                         + K + akoff) * 2;
                LDM_X4(ah[mt][0], ah[mt][1], ah[mt][2], ah[mt][3], sb + SM_AH + ao);
                LDM_X4(al[mt][0], al[mt][1], al[mt][2], al[mt][3], sb + SM_AL + ao);
            }
#pragma unroll
            for (int nt = 0; nt < 6; nt++) {
                uint32_t bo = (uint32_t)((wn * 48 + nt * 8 + bi) * PAD
                                         + K + bh8) * 2;
                uint32_t bh[2], bl[2];
                LDM_X2(bh[0], bh[1], sb + SM_BH + bo);
                LDM_X2(bl[0], bl[1], sb + SM_BL + bo);
#pragma unroll
                for (int mt = 0; mt < 2; mt++) {
                    MMA_BF16(acc[mt][nt], ah[mt], bh);
                    MMA_BF16(acc[mt][nt], ah[mt], bl);
                    MMA_BF16(acc[mt][nt], al[mt], bh);
                }
            }
        }
    }

    const int g = lane >> 2, t = lane & 3;
#pragma unroll
    for (int mt = 0; mt < 2; mt++) {
#pragma unroll
        for (int nt = 0; nt < 6; nt++) {
            const int c0 = wn * 48 + nt * 8 + 2 * t;
            const size_t row = (size_t)m0 + wm * 32 + mt * 16 + g;
            if (c0 < 128) {
                __nv_bfloat16* dh = (c0 < 64) ? g_qh : g_kh;
                __nv_bfloat16* dl = (c0 < 64) ? g_ql : g_kl;
                const int cc = c0 & 63;
                uint32_t h, l;
                split2(acc[mt][nt][0], acc[mt][nt][1], h, l);
                *(uint32_t*)(dh + row * Hn + cc) = h;
                *(uint32_t*)(dl + row * Hn + cc) = l;
                split2(acc[mt][nt][2], acc[mt][nt][3], h, l);
                *(uint32_t*)(dh + (row + 8) * Hn + cc) = h;
                *(uint32_t*)(dl + (row + 8) * Hn + cc) = l;
            } else {
                const int cc = c0 - 128;
                const size_t bb = row >> 10;
#pragma unroll
                for (int rr = 0; rr < 2; rr++) {
                    const size_t s = (row + rr * 8) & 1023;
                    float f0 = acc[mt][nt][rr * 2], f1 = acc[mt][nt][rr * 2 + 1];
                    __nv_bfloat16 h0 = __float2bfloat16(f0);
                    __nv_bfloat16 h1 = __float2bfloat16(f1);
                    g_vth[bb * 65536 + (size_t)cc * 1024 + s] = h0;
                    g_vtl[bb * 65536 + (size_t)cc * 1024 + s] =
                        __float2bfloat16(f0 - __bfloat162float(h0));
                    g_vth[bb * 65536 + (size_t)(cc + 1) * 1024 + s] = h1;
                    g_vtl[bb * 65536 + (size_t)(cc + 1) * 1024 + s] =
                        __float2bfloat16(f1 - __bfloat162float(h1));
                }
            }
        }
    }
}

// ---------------------------------------------------------------------------
// Tensor-core split-KV attention + fused combine. grid (40, 8), 256 threads.
// ---------------------------------------------------------------------------
#define PADH 72
#define SM_QH  0
#define SM_QL  9216
#define SM_KH  18432
#define SM_KL  27648
#define SM_VTH 36864
#define SM_VTL 46080
#define SM_PH  55296
#define SM_PL  64512
#define SM_SS  73728      // fp32 [64][68]
#define SM_DS  91136      // fp32 [64][68]
#define SM_CORR 108544    // fp32 [64]
#define SM_FLAG 108800    // int
#define ATTN_SMEM 108816

__global__ __launch_bounds__(256) void attn_part_kernel(
    const float* __restrict__ rpe, float* __restrict__ out)
{
    extern __shared__ char smem[];
    const uint32_t sb = smem_u32(smem);
    float* Ss = (float*)(smem + SM_SS);
    float* Ds = (float*)(smem + SM_DS);
    float* Cs = (float*)(smem + SM_CORR);

    const int w = blockIdx.x, b = blockIdx.y;
    const int qt = c_qt[w], ch = c_ch[w];
    const int kt0 = ch * 4;
    const int kt1 = min(qt, kt0 + 3);
    const int nch = (qt >> 2) + 1;

    const int tid = threadIdx.x;
    const int wid = tid >> 5, lane = tid & 31;
    const int wm = wid >> 2, wn = wid & 3;
    const int g = lane >> 2, t = lane & 3;
    const int aq = lane >> 3, ai = lane & 7;
    const int arow_off = (aq & 1) * 8 + ai;
    const int akoff = (aq >> 1) * 8;
    const int bi = lane & 7, bh8 = ((lane >> 3) & 1) * 8;

    const int tg = tid >> 4, cg = tid & 15;
    const int tr = tg << 2, sc0 = cg << 2;
    const int row0 = b * Tn + qt * 64;

    // ---- load Q (hi/lo) ----
#pragma unroll
    for (int it = 0; it < 2; it++) {
        int f = it * 256 + tid;
        int r = f >> 3, cq = f & 7;
        uint32_t off = (uint32_t)(r * PADH + cq * 8) * 2;
        *(uint4*)(smem + SM_QH + off) =
            *(const uint4*)(g_qh + (size_t)(row0 + r) * Hn + cq * 8);
        *(uint4*)(smem + SM_QL + off) =
            *(const uint4*)(g_ql + (size_t)(row0 + r) * Hn + cq * 8);
    }
    // ---- E (hi/lo) into K buffers, rows >= 50 zero ----
#pragma unroll
    for (int it = 0; it < 4; it++) {
        int f = it * 256 + tid;
        int r = f >> 4, cq = (f & 15) << 2;
        float4 v = make_float4(0.f, 0.f, 0.f, 0.f);
        if (r < NREL) v = *(const float4*)(rpe + (size_t)r * Hn + cq);
        uint32_t h0, l0, h1, l1;
        split2(v.x, v.y, h0, l0);
        split2(v.z, v.w, h1, l1);
        uint32_t off = (uint32_t)(r * PADH + cq) * 2;
        *(uint2*)(smem + SM_KH + off) = make_uint2(h0, h1);
        *(uint2*)(smem + SM_KL + off) = make_uint2(l0, l1);
    }
    __syncthreads();

    // ---- bias GEMM: Ds = Q E^T ----
    {
        float dacc[2][2][4];
#pragma unroll
        for (int mt = 0; mt < 2; mt++)
#pragma unroll
            for (int nt = 0; nt < 2; nt++)
#pragma unroll
                for (int e = 0; e < 4; e++) dacc[mt][nt][e] = 0.f;
#pragma unroll
        for (int ks = 0; ks < 4; ks++) {
            const int K = ks * 16;
            uint32_t ah[2][4], al[2][4];
#pragma unroll
            for (int mt = 0; mt < 2; mt++) {
                uint32_t ao = (uint32_t)((wm * 32 + mt * 16 + arow_off) * PADH
                                         + K + akoff) * 2;
                LDM_X4(ah[mt][0], ah[mt][1], ah[mt][2], ah[mt][3], sb + SM_QH + ao);
                LDM_X4(al[mt][0], al[mt][1], al[mt][2], al[mt][3], sb + SM_QL + ao);
            }
#pragma unroll
            for (int nt = 0; nt < 2; nt++) {
                uint32_t bo = (uint32_t)((wn * 16 + nt * 8 + bi) * PADH
                                         + K + bh8) * 2;
                uint32_t bh[2], bl[2];
                LDM_X2(bh[0], bh[1], sb + SM_KH + bo);
                LDM_X2(bl[0], bl[1], sb + SM_KL + bo);
#pragma unroll
                for (int mt = 0; mt < 2; mt++) {
                    MMA_BF16(dacc[mt][nt], ah[mt], bh);
                    MMA_BF16(dacc[mt][nt], ah[mt], bl);
                    MMA_BF16(dacc[mt][nt], al[mt], bh);
                }
            }
        }
#pragma unroll
        for (int mt = 0; mt < 2; mt++)
#pragma unroll
            for (int nt = 0; nt < 2; nt++) {
                int row = wm * 32 + mt * 16 + g, col = wn * 16 + nt * 8 + 2 * t;
                *(float2*)&Ds[row * 68 + col] =
                    make_float2(dacc[mt][nt][0], dacc[mt][nt][1]);
                *(float2*)&Ds[(row + 8) * 68 + col] =
                    make_float2(dacc[mt][nt][2], dacc[mt][nt][3]);
            }
    }

    float mrow[4], lrow[4];
#pragma unroll
    for (int i = 0; i < 4; i++) { mrow[i] = -INFINITY; lrow[i] = 0.f; }
    float acc_o[2][2][4];
#pragma unroll
    for (int mt = 0; mt < 2; mt++)
#pragma unroll
        for (int nt = 0; nt < 2; nt++)
#pragma unroll
            for (int e = 0; e < 4; e++) acc_o[mt][nt][e] = 0.f;

    for (int kt = kt0; kt <= kt1; kt++) {
        __syncthreads();
        const int krow0 = b * Tn + kt * 64;
#pragma unroll
        for (int it = 0; it < 2; it++) {
            int f = it * 256 + tid;
            int r = f >> 3, cq = f & 7;
            uint32_t off = (uint32_t)(r * PADH + cq * 8) * 2;
            *(uint4*)(smem + SM_KH + off) =
                *(const uint4*)(g_kh + (size_t)(krow0 + r) * Hn + cq * 8);
            *(uint4*)(smem + SM_KL + off) =
                *(const uint4*)(g_kl + (size_t)(krow0 + r) * Hn + cq * 8);
            *(uint4*)(smem + SM_VTH + off) =
                *(const uint4*)(g_vth + (size_t)b * 65536 + (size_t)r * 1024
                                + kt * 64 + cq * 8);
            *(uint4*)(smem + SM_VTL + off) =
                *(const uint4*)(g_vtl + (size_t)b * 65536 + (size_t)r * 1024
                                + kt * 64 + cq * 8);
        }
        __syncthreads();

        // ---- S = Q K^T ----
        float sacc[2][2][4];
#pragma unroll
        for (int mt = 0; mt < 2; mt++)
#pragma unroll
            for (int nt = 0; nt < 2; nt++)
#pragma unroll
                for (int e = 0; e < 4; e++) sacc[mt][nt][e] = 0.f;
#pragma unroll
        for (int ks = 0; ks < 4; ks++) {
            const int K = ks * 16;
            uint32_t ah[2][4], al[2][4];
#pragma unroll
            for (int mt = 0; mt < 2; mt++) {
                uint32_t ao = (uint32_t)((wm * 32 + mt * 16 + arow_off) * PADH
                                         + K + akoff) * 2;
                LDM_X4(ah[mt][0], ah[mt][1], ah[mt][2], ah[mt][3], sb + SM_QH + ao);
                LDM_X4(al[mt][0], al[mt][1], al[mt][2], al[mt][3], sb + SM_QL + ao);
            }
#pragma unroll
            for (int nt = 0; nt < 2; nt++) {
                uint32_t bo = (uint32_t)((wn * 16 + nt * 8 + bi) * PADH
                                         + K + bh8) * 2;
                uint32_t bh[2], bl[2];
                LDM_X2(bh[0], bh[1], sb + SM_KH + bo);
                LDM_X2(bl[0], bl[1], sb + SM_KL + bo);
#pragma unroll
                for (int mt = 0; mt < 2; mt++) {
                    MMA_BF16(sacc[mt][nt], ah[mt], bh);
                    MMA_BF16(sacc[mt][nt], ah[mt], bl);
                    MMA_BF16(sacc[mt][nt], al[mt], bh);
                }
            }
        }
#pragma unroll
        for (int mt = 0; mt < 2; mt++)
#pragma unroll
            for (int nt = 0; nt < 2; nt++) {
                int row = wm * 32 + mt * 16 + g, col = wn * 16 + nt * 8 + 2 * t;
                *(float2*)&Ss[row * 68 + col] =
                    make_float2(sacc[mt][nt][0], sacc[mt][nt][1]);
                *(float2*)&Ss[(row + 8) * 68 + col] =
                    make_float2(sacc[mt][nt][2], sacc[mt][nt][3]);
            }
        __syncthreads();

        // ---- softmax ----
#pragma unroll
        for (int i = 0; i < 4; i++) {
            const int t_g = qt * 64 + tr + i;
            float sv[4];
            float4 s4 = *(const float4*)&Ss[(tr + i) * 68 + sc0];
            sv[0] = s4.x; sv[1] = s4.y; sv[2] = s4.z; sv[3] = s4.w;
#pragma unroll
            for (int j = 0; j < 4; j++) {
                const int s_g = kt * 64 + sc0 + j;
                int rel = 49 + s_g - t_g;
                rel = rel < 0 ? 0 : (rel > 49 ? 49 : rel);
                float bias = Ds[(tr + i) * 68 + rel];
                sv[j] = (s_g > t_g) ? -INFINITY : fmaf(sv[j], QK_SCALE, bias);
            }
            float rm = fmaxf(fmaxf(sv[0], sv[1]), fmaxf(sv[2], sv[3]));
#pragma unroll
            for (int o = 1; o < 16; o <<= 1)
                rm = fmaxf(rm, __shfl_xor_sync(0xffffffffu, rm, o));
            float mnew = fmaxf(mrow[i], rm);
            float corr = __expf(mrow[i] - mnew);
            float p0 = __expf(sv[0] - mnew);
            float p1 = __expf(sv[1] - mnew);
            float p2 = __expf(sv[2] - mnew);
            float p3 = __expf(sv[3] - mnew);
            uint32_t h0, l0, h1, l1;
            split2(p0, p1, h0, l0);
            split2(p2, p3, h1, l1);
            uint32_t off = (uint32_t)((tr + i) * PADH + sc0) * 2;
            *(uint2*)(smem + SM_PH + off) = make_uint2(h0, h1);
            *(uint2*)(smem + SM_PL + off) = make_uint2(l0, l1);
            float ps = p0 + p1 + p2 + p3;
#pragma unroll
            for (int o = 1; o < 16; o <<= 1)
                ps += __shfl_xor_sync(0xffffffffu, ps, o);
            lrow[i] = lrow[i] * corr + ps;
            mrow[i] = mnew;
            if (cg == 0) Cs[tr + i] = corr;
        }
        __syncthreads();

        // ---- scale O, O += P V ----
#pragma unroll
        for (int mt = 0; mt < 2; mt++) {
            float c0r = Cs[wm * 32 + mt * 16 + g];
            float c1r = Cs[wm * 32 + mt * 16 + g + 8];
#pragma unroll
            for (int nt = 0; nt < 2; nt++) {
                acc_o[mt][nt][0] *= c0r; acc_o[mt][nt][1] *= c0r;
                acc_o[mt][nt][2] *= c1r; acc_o[mt][nt][3] *= c1r;
            }
        }
#pragma unroll
        for (int ks = 0; ks < 4; ks++) {
            const int K = ks * 16;
            uint32_t ah[2][4], al[2][4];
#pragma unroll
            for (int mt = 0; mt < 2; mt++) {
                uint32_t ao = (uint32_t)((wm * 32 + mt * 16 + arow_off) * PADH
                                         + K + akoff) * 2;
                LDM_X4(ah[mt][0], ah[mt][1], ah[mt][2], ah[mt][3], sb + SM_PH + ao);
                LDM_X4(al[mt][0], al[mt][1], al[mt][2], al[mt][3], sb + SM_PL + ao);
            }
#pragma unroll
            for (int nt = 0; nt < 2; nt++) {
                uint32_t bo = (uint32_t)((wn * 16 + nt * 8 + bi) * PADH
                                         + K + bh8) * 2;
                uint32_t bh[2], bl[2];
                LDM_X2(bh[0], bh[1], sb + SM_VTH + bo);
                LDM_X2(bl[0], bl[1], sb + SM_VTL + bo);
#pragma unroll
                for (int mt = 0; mt < 2; mt++) {
                    MMA_BF16(acc_o[mt][nt], ah[mt], bh);
                    MMA_BF16(acc_o[mt][nt], ah[mt], bl);
                    MMA_BF16(acc_o[mt][nt], al[mt], bh);
                }
            }
        }
    }

    // ================= epilogue =================
    __syncthreads();

    if (nch == 1) {
        if (cg == 0) {
#pragma unroll
            for (int i = 0; i < 4; i++) Cs[tr + i] = lrow[i];
        }
        __syncthreads();
#pragma unroll
        for (int mt = 0; mt < 2; mt++)
#pragma unroll
            for (int nt = 0; nt < 2; nt++) {
                int row = wm * 32 + mt * 16 + g, col = wn * 16 + nt * 8 + 2 * t;
                float i0 = 1.f / Cs[row], i1 = 1.f / Cs[row + 8];
                *(float2*)(out + (size_t)(row0 + row) * Hn + col) =
                    make_float2(acc_o[mt][nt][0] * i0, acc_o[mt][nt][1] * i0);
                *(float2*)(out + (size_t)(row0 + row + 8) * Hn + col) =
                    make_float2(acc_o[mt][nt][2] * i1, acc_o[mt][nt][3] * i1);
            }
        return;
    }

    const int slot = (b * NQT + qt) * NCH + ch;
    float* pa = g_pacc[slot];
#pragma unroll
    for (int mt = 0; mt < 2; mt++)
#pragma unroll
        for (int nt = 0; nt < 2; nt++) {
            int row = wm * 32 + mt * 16 + g, col = wn * 16 + nt * 8 + 2 * t;
            *(float2*)(pa + row * 64 + col) =
                make_float2(acc_o[mt][nt][0], acc_o[mt][nt][1]);
            *(float2*)(pa + (row + 8) * 64 + col) =
                make_float2(acc_o[mt][nt][2], acc_o[mt][nt][3]);
        }
    if (cg == 0) {
#pragma unroll
        for (int i = 0; i < 4; i++) {
            g_pm[slot][tr + i] = mrow[i];
            g_pl[slot][tr + i] = lrow[i];
        }
    }
    __threadfence();
    if (tid == 0) {
        int old = atomicAdd(&g_cnt[b * NQT + qt], 1);
        *(int*)(smem + SM_FLAG) = (old == nch - 1);
    }
    __syncthreads();
    if (!*(int*)(smem + SM_FLAG)) return;
    __threadfence();

    const int base = (b * NQT + qt) * NCH;
    const int r = tid >> 2, hc = (tid & 3) << 4;
    float m[NCH], wgt[NCH];
    float M = -INFINITY;
    for (int c = 0; c < nch; c++) {
        m[c] = g_pm[base + c][r];
        M = fmaxf(M, m[c]);
    }
    float L = 0.f;
    for (int c = 0; c < nch; c++) {
        wgt[c] = __expf(m[c] - M);
        L += g_pl[base + c][r] * wgt[c];
    }
    float invL = 1.f / L;
    float4 o[4];
#pragma unroll
    for (int j = 0; j < 4; j++) o[j] = make_float4(0.f, 0.f, 0.f, 0.f);
    for (int c = 0; c < nch; c++) {
        const float wc = wgt[c] * invL;
        const float* pc = g_pacc[base + c] + r * 64 + hc;
#pragma unroll
        for (int j = 0; j < 4; j++) {
            float4 v = *(const float4*)(pc + 4 * j);
            o[j].x = fmaf(wc, v.x, o[j].x);
            o[j].y = fmaf(wc, v.y, o[j].y);
            o[j].z = fmaf(wc, v.z, o[j].z);
            o[j].w = fmaf(wc, v.w, o[j].w);
        }
    }
    float* op = out + (size_t)(row0 + r) * Hn + hc;
#pragma unroll
    for (int j = 0; j < 4; j++)
        *(float4*)(op + 4 * j) = o[j];
}

extern "C" void kernel_launch(void* const* d_in, const int* in_sizes, int n_in,
                              void* d_out, int out_size)
{
    const float* x   = (const float*)d_in[0];
    const float* Wq  = (const float*)d_in[1];
    const float* Wk  = (const float*)d_in[2];
    const float* Wv  = (const float*)d_in[3];
    const float* rpe = (const float*)d_in[4];
    float* out = (float*)d_out;

    cudaFuncSetAttribute(qkv_mma_kernel,
                         cudaFuncAttributeMaxDynamicSharedMemorySize, QKV_SMEM);
    cudaFuncSetAttribute(attn_part_kernel,
                         cudaFuncAttributeMaxDynamicSharedMemorySize, ATTN_SMEM);

    cvt_w_kernel<<<24, 256>>>(Wq, Wk, Wv);
    qkv_mma_kernel<<<128, 256, QKV_SMEM>>>(x);
    attn_part_kernel<<<dim3(NWORK, 8), 256, ATTN_SMEM>>>(rpe, out);
}

// round 9
// speedup vs baseline: 1.0611x; 1.0611x over previous
#include <cuda_runtime.h>
#include <cuda_bf16.h>
#include <math.h>
#include <stdint.h>

#define Bn 8
#define Tn 1024
#define Cn 512
#define Hn 64
#define NREL 50
#define QK_SCALE 0.125f   // 64^-0.5
#define NQT 16
#define NCH 4
#define NWORK 40

// split-bf16 q,k (row-major [B*T][64]) and v transposed ([B][64][T])
__device__ __nv_bfloat16 g_qh[Bn * Tn * Hn];
__device__ __nv_bfloat16 g_ql[Bn * Tn * Hn];
__device__ __nv_bfloat16 g_kh[Bn * Tn * Hn];
__device__ __nv_bfloat16 g_kl[Bn * Tn * Hn];
__device__ __nv_bfloat16 g_vth[Bn * Hn * Tn];
__device__ __nv_bfloat16 g_vtl[Bn * Hn * Tn];

// split-bf16 W^T
__device__ __nv_bfloat16 g_wth[192 * Cn];
__device__ __nv_bfloat16 g_wtl[192 * Cn];

// split-KV partials
__device__ float g_pacc[Bn * NQT * NCH][64 * 64];
__device__ float g_pm[Bn * NQT * NCH][64];
__device__ float g_pl[Bn * NQT * NCH][64];

__constant__ unsigned char c_qt[NWORK] = {
    0,1,2,3, 4,4, 5,5, 6,6, 7,7,
    8,8,8, 9,9,9, 10,10,10, 11,11,11,
    12,12,12,12, 13,13,13,13, 14,14,14,14, 15,15,15,15};
__constant__ unsigned char c_ch[NWORK] = {
    0,0,0,0, 0,1, 0,1, 0,1, 0,1,
    0,1,2, 0,1,2, 0,1,2, 0,1,2,
    0,1,2,3, 0,1,2,3, 0,1,2,3, 0,1,2,3};

// ---------------------------------------------------------------------------
// helpers
// ---------------------------------------------------------------------------
__device__ __forceinline__ uint32_t smem_u32(const void* p) {
    uint32_t a;
    asm("{ .reg .u64 t; cvta.to.shared.u64 t, %1; cvt.u32.u64 %0, t; }"
        : "=r"(a) : "l"(p));
    return a;
}
#define LDM_X4(r0, r1, r2, r3, a) \
    asm volatile("ldmatrix.sync.aligned.m8n8.x4.shared.b16 {%0,%1,%2,%3}, [%4];" \
                 : "=r"(r0), "=r"(r1), "=r"(r2), "=r"(r3) : "r"(a))
#define LDM_X2(r0, r1, a) \
    asm volatile("ldmatrix.sync.aligned.m8n8.x2.shared.b16 {%0,%1}, [%2];" \
                 : "=r"(r0), "=r"(r1) : "r"(a))
#define MMA_BF16(d, a, b) \
    asm volatile("mma.sync.aligned.m16n8k16.row.col.f32.bf16.bf16.f32 " \
                 "{%0,%1,%2,%3}, {%4,%5,%6,%7}, {%8,%9}, {%0,%1,%2,%3};" \
                 : "+f"((d)[0]), "+f"((d)[1]), "+f"((d)[2]), "+f"((d)[3]) \
                 : "r"((a)[0]), "r"((a)[1]), "r"((a)[2]), "r"((a)[3]), \
                   "r"((b)[0]), "r"((b)[1]))

__device__ __forceinline__ void split2(float f0, float f1,
                                       uint32_t& h, uint32_t& l) {
    __nv_bfloat16 h0 = __float2bfloat16(f0), h1 = __float2bfloat16(f1);
    __nv_bfloat16 l0 = __float2bfloat16(f0 - __bfloat162float(h0));
    __nv_bfloat16 l1 = __float2bfloat16(f1 - __bfloat162float(h1));
    __nv_bfloat162 hh(h0, h1), ll(l0, l1);
    h = *(uint32_t*)&hh; l = *(uint32_t*)&ll;
}

// ---------------------------------------------------------------------------
// Weight convert + transpose. grid 24, 1024 threads.
// Block = (mat, ktile of 64): one coalesced float4 read per thread,
// smem transpose, coalesced uint4 writes.
// ---------------------------------------------------------------------------
__global__ __launch_bounds__(1024) void cvt_w_kernel(
    const float* __restrict__ Wq, const float* __restrict__ Wk,
    const float* __restrict__ Wv)
{
    __shared__ __nv_bfloat16 th[64][72];   // [n][k]
    __shared__ __nv_bfloat16 tl[64][72];
    const int mat = blockIdx.x >> 3, kt = blockIdx.x & 7;
    const float* W = (mat == 0) ? Wq : (mat == 1 ? Wk : Wv);
    const int tid = threadIdx.x;

    {
        int k = tid >> 4, nn = (tid & 15) << 2;
        float4 v = *(const float4*)(W + (size_t)(kt * 64 + k) * Hn + nn);
        float vv[4] = {v.x, v.y, v.z, v.w};
#pragma unroll
        for (int j = 0; j < 4; j++) {
            __nv_bfloat16 h = __float2bfloat16(vv[j]);
            th[nn + j][k] = h;
            tl[nn + j][k] = __float2bfloat16(vv[j] - __bfloat162float(h));
        }
    }
    __syncthreads();
    {
        int n = (tid & 511) >> 3, kk = (tid & 7) << 3;
        size_t dst = (size_t)(mat * 64 + n) * Cn + kt * 64 + kk;
        if (tid < 512) *(uint4*)(g_wth + dst) = *(uint4*)&th[n][kk];
        else           *(uint4*)(g_wtl + dst) = *(uint4*)&tl[n][kk];
    }
}

// ---------------------------------------------------------------------------
// QKV projection on mma.sync bf16 (split hi/lo). grid 128, 256 threads.
// ---------------------------------------------------------------------------
#define PAD 72
#define SM_AH 0
#define SM_AL 9216
#define SM_BH 18432
#define SM_BL 46080
#define QKV_SMEM 73728

__global__ __launch_bounds__(256, 1) void qkv_mma_kernel(const float* __restrict__ x)
{
    extern __shared__ char smem[];
    const uint32_t sb = smem_u32(smem);
    const int tid = threadIdx.x;
    const int wid = tid >> 5, lane = tid & 31;
    const int wm = wid >> 2, wn = wid & 3;
    const int m0 = blockIdx.x * 64;

    float acc[2][6][4];
#pragma unroll
    for (int mt = 0; mt < 2; mt++)
#pragma unroll
        for (int nt = 0; nt < 6; nt++)
#pragma unroll
            for (int e = 0; e < 4; e++) acc[mt][nt][e] = 0.f;

    const int aq = lane >> 3, ai = lane & 7;
    const int arow_off = (aq & 1) * 8 + ai;
    const int akoff = (aq >> 1) * 8;
    const int bi = lane & 7, bh8 = ((lane >> 3) & 1) * 8;

    for (int c = 0; c < 8; c++) {
        if (c) __syncthreads();
        const int kc = c * 64;
#pragma unroll
        for (int it = 0; it < 4; it++) {
            int f = it * 256 + tid;
            int r = f >> 4, kq = (f & 15) << 2;
            float4 v = *(const float4*)(x + (size_t)(m0 + r) * Cn + kc + kq);
            uint32_t h0, l0, h1, l1;
            split2(v.x, v.y, h0, l0);
            split2(v.z, v.w, h1, l1);
            uint32_t off = (uint32_t)(r * PAD + kq) * 2;
            *(uint2*)(smem + SM_AH + off) = make_uint2(h0, h1);
            *(uint2*)(smem + SM_AL + off) = make_uint2(l0, l1);
        }
#pragma unroll
        for (int it = 0; it < 6; it++) {
            int f = it * 256 + tid;
            int n = f >> 3, kq = (f & 7) << 3;
            uint32_t off = (uint32_t)(n * PAD + kq) * 2;
            *(uint4*)(smem + SM_BH + off) =
                *(const uint4*)(g_wth + (size_t)n * Cn + kc + kq);
            *(uint4*)(smem + SM_BL + off) =
                *(const uint4*)(g_wtl + (size_t)n * Cn + kc + kq);
        }
        __syncthreads();

#pragma unroll
        for (int ks = 0; ks < 4; ks++) {
            const int K = ks * 16;
            uint32_t ah[2][4], al[2][4];
#pragma unroll
            for (int mt = 0; mt < 2; mt++) {
                uint32_t ao = (uint32_t)((wm * 32 + mt * 16 + arow_off) * PAD
                                         + K + akoff) * 2;
                LDM_X4(ah[mt][0], ah[mt][1], ah[mt][2], ah[mt][3], sb + SM_AH + ao);
                LDM_X4(al[mt][0], al[mt][1], al[mt][2], al[mt][3], sb + SM_AL + ao);
            }
#pragma unroll
            for (int nt = 0; nt < 6; nt++) {
                uint32_t bo = (uint32_t)((wn * 48 + nt * 8 + bi) * PAD
                                         + K + bh8) * 2;
                uint32_t bh[2], bl[2];
                LDM_X2(bh[0], bh[1], sb + SM_BH + bo);
                LDM_X2(bl[0], bl[1], sb + SM_BL + bo);
#pragma unroll
                for (int mt = 0; mt < 2; mt++) {
                    MMA_BF16(acc[mt][nt], ah[mt], bh);
                    MMA_BF16(acc[mt][nt], ah[mt], bl);
                    MMA_BF16(acc[mt][nt], al[mt], bh);
                }
            }
        }
    }

    const int g = lane >> 2, t = lane & 3;
#pragma unroll
    for (int mt = 0; mt < 2; mt++) {
#pragma unroll
        for (int nt = 0; nt < 6; nt++) {
            const int c0 = wn * 48 + nt * 8 + 2 * t;
            const size_t row = (size_t)m0 + wm * 32 + mt * 16 + g;
            if (c0 < 128) {
                __nv_bfloat16* dh = (c0 < 64) ? g_qh : g_kh;
                __nv_bfloat16* dl = (c0 < 64) ? g_ql : g_kl;
                const int cc = c0 & 63;
                uint32_t h, l;
                split2(acc[mt][nt][0], acc[mt][nt][1], h, l);
                *(uint32_t*)(dh + row * Hn + cc) = h;
                *(uint32_t*)(dl + row * Hn + cc) = l;
                split2(acc[mt][nt][2], acc[mt][nt][3], h, l);
                *(uint32_t*)(dh + (row + 8) * Hn + cc) = h;
                *(uint32_t*)(dl + (row + 8) * Hn + cc) = l;
            } else {
                const int cc = c0 - 128;
                const size_t bb = row >> 10;
#pragma unroll
                for (int rr = 0; rr < 2; rr++) {
                    const size_t s = (row + rr * 8) & 1023;
                    float f0 = acc[mt][nt][rr * 2], f1 = acc[mt][nt][rr * 2 + 1];
                    __nv_bfloat16 h0 = __float2bfloat16(f0);
                    __nv_bfloat16 h1 = __float2bfloat16(f1);
                    g_vth[bb * 65536 + (size_t)cc * 1024 + s] = h0;
                    g_vtl[bb * 65536 + (size_t)cc * 1024 + s] =
                        __float2bfloat16(f0 - __bfloat162float(h0));
                    g_vth[bb * 65536 + (size_t)(cc + 1) * 1024 + s] = h1;
                    g_vtl[bb * 65536 + (size_t)(cc + 1) * 1024 + s] =
                        __float2bfloat16(f1 - __bfloat162float(h1));
                }
            }
        }
    }
}

// ---------------------------------------------------------------------------
// Tensor-core split-KV attention partials. grid (40, 8), 256 threads.
// nch==1 tiles write final output directly; others write raw partials.
// ---------------------------------------------------------------------------
#define PADH 72
#define SM_QH  0
#define SM_QL  9216
#define SM_KH  18432
#define SM_KL  27648
#define SM_VTH 36864
#define SM_VTL 46080
#define SM_PH  55296
#define SM_PL  64512
#define SM_SS  73728      // fp32 [64][68]
#define SM_DS  91136      // fp32 [64][68]
#define SM_CORR 108544    // fp32 [64]
#define ATTN_SMEM 108800

__global__ __launch_bounds__(256) void attn_part_kernel(
    const float* __restrict__ rpe, float* __restrict__ out)
{
    extern __shared__ char smem[];
    const uint32_t sb = smem_u32(smem);
    float* Ss = (float*)(smem + SM_SS);
    float* Ds = (float*)(smem + SM_DS);
    float* Cs = (float*)(smem + SM_CORR);

    const int w = blockIdx.x, b = blockIdx.y;
    const int qt = c_qt[w], ch = c_ch[w];
    const int kt0 = ch * 4;
    const int kt1 = min(qt, kt0 + 3);
    const int nch = (qt >> 2) + 1;

    const int tid = threadIdx.x;
    const int wid = tid >> 5, lane = tid & 31;
    const int wm = wid >> 2, wn = wid & 3;
    const int g = lane >> 2, t = lane & 3;
    const int aq = lane >> 3, ai = lane & 7;
    const int arow_off = (aq & 1) * 8 + ai;
    const int akoff = (aq >> 1) * 8;
    const int bi = lane & 7, bh8 = ((lane >> 3) & 1) * 8;

    const int tg = tid >> 4, cg = tid & 15;
    const int tr = tg << 2, sc0 = cg << 2;
    const int row0 = b * Tn + qt * 64;

    // ---- load Q (hi/lo) ----
#pragma unroll
    for (int it = 0; it < 2; it++) {
        int f = it * 256 + tid;
        int r = f >> 3, cq = f & 7;
        uint32_t off = (uint32_t)(r * PADH + cq * 8) * 2;
        *(uint4*)(smem + SM_QH + off) =
            *(const uint4*)(g_qh + (size_t)(row0 + r) * Hn + cq * 8);
        *(uint4*)(smem + SM_QL + off) =
            *(const uint4*)(g_ql + (size_t)(row0 + r) * Hn + cq * 8);
    }
    // ---- E (hi/lo) into K buffers, rows >= 50 zero ----
#pragma unroll
    for (int it = 0; it < 4; it++) {
        int f = it * 256 + tid;
        int r = f >> 4, cq = (f & 15) << 2;
        float4 v = make_float4(0.f, 0.f, 0.f, 0.f);
        if (r < NREL) v = *(const float4*)(rpe + (size_t)r * Hn + cq);
        uint32_t h0, l0, h1, l1;
        split2(v.x, v.y, h0, l0);
        split2(v.z, v.w, h1, l1);
        uint32_t off = (uint32_t)(r * PADH + cq) * 2;
        *(uint2*)(smem + SM_KH + off) = make_uint2(h0, h1);
        *(uint2*)(smem + SM_KL + off) = make_uint2(l0, l1);
    }
    __syncthreads();

    // ---- bias GEMM: Ds = Q E^T ----
    {
        float dacc[2][2][4];
#pragma unroll
        for (int mt = 0; mt < 2; mt++)
#pragma unroll
            for (int nt = 0; nt < 2; nt++)
#pragma unroll
                for (int e = 0; e < 4; e++) dacc[mt][nt][e] = 0.f;
#pragma unroll
        for (int ks = 0; ks < 4; ks++) {
            const int K = ks * 16;
            uint32_t ah[2][4], al[2][4];
#pragma unroll
            for (int mt = 0; mt < 2; mt++) {
                uint32_t ao = (uint32_t)((wm * 32 + mt * 16 + arow_off) * PADH
                                         + K + akoff) * 2;
                LDM_X4(ah[mt][0], ah[mt][1], ah[mt][2], ah[mt][3], sb + SM_QH + ao);
                LDM_X4(al[mt][0], al[mt][1], al[mt][2], al[mt][3], sb + SM_QL + ao);
            }
#pragma unroll
            for (int nt = 0; nt < 2; nt++) {
                uint32_t bo = (uint32_t)((wn * 16 + nt * 8 + bi) * PADH
                                         + K + bh8) * 2;
                uint32_t bh[2], bl[2];
                LDM_X2(bh[0], bh[1], sb + SM_KH + bo);
                LDM_X2(bl[0], bl[1], sb + SM_KL + bo);
#pragma unroll
                for (int mt = 0; mt < 2; mt++) {
                    MMA_BF16(dacc[mt][nt], ah[mt], bh);
                    MMA_BF16(dacc[mt][nt], ah[mt], bl);
                    MMA_BF16(dacc[mt][nt], al[mt], bh);
                }
            }
        }
#pragma unroll
        for (int mt = 0; mt < 2; mt++)
#pragma unroll
            for (int nt = 0; nt < 2; nt++) {
                int row = wm * 32 + mt * 16 + g, col = wn * 16 + nt * 8 + 2 * t;
                *(float2*)&Ds[row * 68 + col] =
                    make_float2(dacc[mt][nt][0], dacc[mt][nt][1]);
                *(float2*)&Ds[(row + 8) * 68 + col] =
                    make_float2(dacc[mt][nt][2], dacc[mt][nt][3]);
            }
    }

    float mrow[4], lrow[4];
#pragma unroll
    for (int i = 0; i < 4; i++) { mrow[i] = -INFINITY; lrow[i] = 0.f; }
    float acc_o[2][2][4];
#pragma unroll
    for (int mt = 0; mt < 2; mt++)
#pragma unroll
        for (int nt = 0; nt < 2; nt++)
#pragma unroll
            for (int e = 0; e < 4; e++) acc_o[mt][nt][e] = 0.f;

    for (int kt = kt0; kt <= kt1; kt++) {
        __syncthreads();
        const int krow0 = b * Tn + kt * 64;
#pragma unroll
        for (int it = 0; it < 2; it++) {
            int f = it * 256 + tid;
            int r = f >> 3, cq = f & 7;
            uint32_t off = (uint32_t)(r * PADH + cq * 8) * 2;
            *(uint4*)(smem + SM_KH + off) =
                *(const uint4*)(g_kh + (size_t)(krow0 + r) * Hn + cq * 8);
            *(uint4*)(smem + SM_KL + off) =
                *(const uint4*)(g_kl + (size_t)(krow0 + r) * Hn + cq * 8);
            *(uint4*)(smem + SM_VTH + off) =
                *(const uint4*)(g_vth + (size_t)b * 65536 + (size_t)r * 1024
                                + kt * 64 + cq * 8);
            *(uint4*)(smem + SM_VTL + off) =
                *(const uint4*)(g_vtl + (size_t)b * 65536 + (size_t)r * 1024
                                + kt * 64 + cq * 8);
        }
        __syncthreads();

        // ---- S = Q K^T ----
        float sacc[2][2][4];
#pragma unroll
        for (int mt = 0; mt < 2; mt++)
#pragma unroll
            for (int nt = 0; nt < 2; nt++)
#pragma unroll
                for (int e = 0; e < 4; e++) sacc[mt][nt][e] = 0.f;
#pragma unroll
        for (int ks = 0; ks < 4; ks++) {
            const int K = ks * 16;
            uint32_t ah[2][4], al[2][4];
#pragma unroll
            for (int mt = 0; mt < 2; mt++) {
                uint32_t ao = (uint32_t)((wm * 32 + mt * 16 + arow_off) * PADH
                                         + K + akoff) * 2;
                LDM_X4(ah[mt][0], ah[mt][1], ah[mt][2], ah[mt][3], sb + SM_QH + ao);
                LDM_X4(al[mt][0], al[mt][1], al[mt][2], al[mt][3], sb + SM_QL + ao);
            }
#pragma unroll
            for (int nt = 0; nt < 2; nt++) {
                uint32_t bo = (uint32_t)((wn * 16 + nt * 8 + bi) * PADH
                                         + K + bh8) * 2;
                uint32_t bh[2], bl[2];
                LDM_X2(bh[0], bh[1], sb + SM_KH + bo);
                LDM_X2(bl[0], bl[1], sb + SM_KL + bo);
#pragma unroll
                for (int mt = 0; mt < 2; mt++) {
                    MMA_BF16(sacc[mt][nt], ah[mt], bh);
                    MMA_BF16(sacc[mt][nt], ah[mt], bl);
                    MMA_BF16(sacc[mt][nt], al[mt], bh);
                }
            }
        }
#pragma unroll
        for (int mt = 0; mt < 2; mt++)
#pragma unroll
            for (int nt = 0; nt < 2; nt++) {
                int row = wm * 32 + mt * 16 + g, col = wn * 16 + nt * 8 + 2 * t;
                *(float2*)&Ss[row * 68 + col] =
                    make_float2(sacc[mt][nt][0], sacc[mt][nt][1]);
                *(float2*)&Ss[(row + 8) * 68 + col] =
                    make_float2(sacc[mt][nt][2], sacc[mt][nt][3]);
            }
        __syncthreads();

        // ---- softmax ----
#pragma unroll
        for (int i = 0; i < 4; i++) {
            const int t_g = qt * 64 + tr + i;
            float sv[4];
            float4 s4 = *(const float4*)&Ss[(tr + i) * 68 + sc0];
            sv[0] = s4.x; sv[1] = s4.y; sv[2] = s4.z; sv[3] = s4.w;
#pragma unroll
            for (int j = 0; j < 4; j++) {
                const int s_g = kt * 64 + sc0 + j;
                int rel = 49 + s_g - t_g;
                rel = rel < 0 ? 0 : (rel > 49 ? 49 : rel);
                float bias = Ds[(tr + i) * 68 + rel];
                sv[j] = (s_g > t_g) ? -INFINITY : fmaf(sv[j], QK_SCALE, bias);
            }
            float rm = fmaxf(fmaxf(sv[0], sv[1]), fmaxf(sv[2], sv[3]));
#pragma unroll
            for (int o = 1; o < 16; o <<= 1)
                rm = fmaxf(rm, __shfl_xor_sync(0xffffffffu, rm, o));
            float mnew = fmaxf(mrow[i], rm);
            float corr = __expf(mrow[i] - mnew);
            float p0 = __expf(sv[0] - mnew);
            float p1 = __expf(sv[1] - mnew);
            float p2 = __expf(sv[2] - mnew);
            float p3 = __expf(sv[3] - mnew);
            uint32_t h0, l0, h1, l1;
            split2(p0, p1, h0, l0);
            split2(p2, p3, h1, l1);
            uint32_t off = (uint32_t)((tr + i) * PADH + sc0) * 2;
            *(uint2*)(smem + SM_PH + off) = make_uint2(h0, h1);
            *(uint2*)(smem + SM_PL + off) = make_uint2(l0, l1);
            float ps = p0 + p1 + p2 + p3;
#pragma unroll
            for (int o = 1; o < 16; o <<= 1)
                ps += __shfl_xor_sync(0xffffffffu, ps, o);
            lrow[i] = lrow[i] * corr + ps;
            mrow[i] = mnew;
            if (cg == 0) Cs[tr + i] = corr;
        }
        __syncthreads();

        // ---- scale O, O += P V ----
#pragma unroll
        for (int mt = 0; mt < 2; mt++) {
            float c0r = Cs[wm * 32 + mt * 16 + g];
            float c1r = Cs[wm * 32 + mt * 16 + g + 8];
#pragma unroll
            for (int nt = 0; nt < 2; nt++) {
                acc_o[mt][nt][0] *= c0r; acc_o[mt][nt][1] *= c0r;
                acc_o[mt][nt][2] *= c1r; acc_o[mt][nt][3] *= c1r;
            }
        }
#pragma unroll
        for (int ks = 0; ks < 4; ks++) {
            const int K = ks * 16;
            uint32_t ah[2][4], al[2][4];
#pragma unroll
            for (int mt = 0; mt < 2; mt++) {
                uint32_t ao = (uint32_t)((wm * 32 + mt * 16 + arow_off) * PADH
                                         + K + akoff) * 2;
                LDM_X4(ah[mt][0], ah[mt][1], ah[mt][2], ah[mt][3], sb + SM_PH + ao);
                LDM_X4(al[mt][0], al[mt][1], al[mt][2], al[mt][3], sb + SM_PL + ao);
            }
#pragma unroll
            for (int nt = 0; nt < 2; nt++) {
                uint32_t bo = (uint32_t)((wn * 16 + nt * 8 + bi) * PADH
                                         + K + bh8) * 2;
                uint32_t bh[2], bl[2];
                LDM_X2(bh[0], bh[1], sb + SM_VTH + bo);
                LDM_X2(bl[0], bl[1], sb + SM_VTL + bo);
#pragma unroll
                for (int mt = 0; mt < 2; mt++) {
                    MMA_BF16(acc_o[mt][nt], ah[mt], bh);
                    MMA_BF16(acc_o[mt][nt], ah[mt], bl);
                    MMA_BF16(acc_o[mt][nt], al[mt], bh);
                }
            }
        }
    }

    // ================= epilogue =================
    __syncthreads();

    if (nch == 1) {
        if (cg == 0) {
#pragma unroll
            for (int i = 0; i < 4; i++) Cs[tr + i] = lrow[i];
        }
        __syncthreads();
#pragma unroll
        for (int mt = 0; mt < 2; mt++)
#pragma unroll
            for (int nt = 0; nt < 2; nt++) {
                int row = wm * 32 + mt * 16 + g, col = wn * 16 + nt * 8 + 2 * t;
                float i0 = 1.f / Cs[row], i1 = 1.f / Cs[row + 8];
                *(float2*)(out + (size_t)(row0 + row) * Hn + col) =
                    make_float2(acc_o[mt][nt][0] * i0, acc_o[mt][nt][1] * i0);
                *(float2*)(out + (size_t)(row0 + row + 8) * Hn + col) =
                    make_float2(acc_o[mt][nt][2] * i1, acc_o[mt][nt][3] * i1);
            }
        return;
    }

    const int slot = (b * NQT + qt) * NCH + ch;
    float* pa = g_pacc[slot];
#pragma unroll
    for (int mt = 0; mt < 2; mt++)
#pragma unroll
        for (int nt = 0; nt < 2; nt++) {
            int row = wm * 32 + mt * 16 + g, col = wn * 16 + nt * 8 + 2 * t;
            *(float2*)(pa + row * 64 + col) =
                make_float2(acc_o[mt][nt][0], acc_o[mt][nt][1]);
            *(float2*)(pa + (row + 8) * 64 + col) =
                make_float2(acc_o[mt][nt][2], acc_o[mt][nt][3]);
        }
    if (cg == 0) {
#pragma unroll
        for (int i = 0; i < 4; i++) {
            g_pm[slot][tr + i] = mrow[i];
            g_pl[slot][tr + i] = lrow[i];
        }
    }
}

// ---------------------------------------------------------------------------
// Combine partials. grid (12, 8) for qt=4..15, 1024 threads.
// Fully unrolled predicated loads -> one latency round per thread.
// ---------------------------------------------------------------------------
__global__ __launch_bounds__(1024) void combine_kernel(float* __restrict__ out)
{
    const int qt = blockIdx.x + 4, b = blockIdx.y;
    const int nch = (qt >> 2) + 1;
    const int base = (b * NQT + qt) * NCH;
    const int tid = threadIdx.x;
    const int r = tid >> 4;
    const int hc = (tid & 15) << 2;

    float m[NCH], l[NCH];
    float4 v[NCH];
#pragma unroll
    for (int c = 0; c < NCH; c++) {
        bool p = c < nch;
        m[c] = p ? g_pm[base + c][r] : -INFINITY;
        l[c] = p ? g_pl[base + c][r] : 0.f;
        v[c] = p ? *(const float4*)(g_pacc[base + c] + r * 64 + hc)
                 : make_float4(0.f, 0.f, 0.f, 0.f);
    }
    float M = fmaxf(fmaxf(m[0], m[1]), fmaxf(m[2], m[3]));
    float wgt[NCH], L = 0.f;
#pragma unroll
    for (int c = 0; c < NCH; c++) {
        wgt[c] = __expf(m[c] - M);
        L = fmaf(l[c], wgt[c], L);
    }
    float invL = 1.f / L;
    float4 o = make_float4(0.f, 0.f, 0.f, 0.f);
#pragma unroll
    for (int c = 0; c < NCH; c++) {
        float wc = wgt[c] * invL;
        o.x = fmaf(wc, v[c].x, o.x);
        o.y = fmaf(wc, v[c].y, o.y);
        o.z = fmaf(wc, v[c].z, o.z);
        o.w = fmaf(wc, v[c].w, o.w);
    }
    *(float4*)(out + (size_t)(b * Tn + qt * 64 + r) * Hn + hc) = o;
}

extern "C" void kernel_launch(void* const* d_in, const int* in_sizes, int n_in,
                              void* d_out, int out_size)
{
    const float* x   = (const float*)d_in[0];
    const float* Wq  = (const float*)d_in[1];
    const float* Wk  = (const float*)d_in[2];
    const float* Wv  = (const float*)d_in[3];
    const float* rpe = (const float*)d_in[4];
    float* out = (float*)d_out;

    cudaFuncSetAttribute(qkv_mma_kernel,
                         cudaFuncAttributeMaxDynamicSharedMemorySize, QKV_SMEM);
    cudaFuncSetAttribute(attn_part_kernel,
                         cudaFuncAttributeMaxDynamicSharedMemorySize, ATTN_SMEM);

    cvt_w_kernel<<<24, 1024>>>(Wq, Wk, Wv);
    qkv_mma_kernel<<<128, 256, QKV_SMEM>>>(x);
    attn_part_kernel<<<dim3(NWORK, 8), 256, ATTN_SMEM>>>(rpe, out);
    combine_kernel<<<dim3(12, 8), 1024>>>(out);
}